// round 11
// baseline (speedup 1.0000x reference)
#include <cuda_runtime.h>
#include <cuda_bf16.h>

// Problem constants
#define T_STEPS 4096
#define M_BATCH 512
#define D_IN    11
#define NH      51
#define G4      204          // 4*NH gate columns
#define A1S     64           // act1 row stride: x[11] | h1[51] | 2 pad
#define A2S     104          // act2 row stride: h1[51] | h2[51] | 2 pad
#define GROWS   2            // rows per group (A: rows 0-1, B: rows 2-3)
#define THREADS 256          // 8 warps; hf = tid>>7; 102 col-pair threads per K-half
#define BLOCKS  128          // 128*4 = 512 rows
#define CP      102          // column-pairs (204/2)

// fast tanh (MUFU.TANH)
__device__ __forceinline__ float tanha(float x) {
    float y;
    asm("tanh.approx.f32 %0, %1;" : "=f"(y) : "f"(x));
    return y;
}
__device__ __forceinline__ float siga(float x) {
    return fmaf(0.5f, tanha(0.5f * x), 0.5f);
}

// packed 2xfp32 FMA (Blackwell f32x2 pipe)
__device__ __forceinline__ unsigned long long fma2(unsigned long long a,
                                                   unsigned long long b,
                                                   unsigned long long c) {
    unsigned long long d;
    asm("fma.rn.f32x2 %0, %1, %2, %3;" : "=l"(d) : "l"(a), "l"(b), "l"(c));
    return d;
}
__device__ __forceinline__ unsigned long long pack2(float lo, float hi) {
    unsigned long long r;
    asm("mov.b64 %0, {%1, %2};" : "=l"(r) : "f"(lo), "f"(hi));
    return r;
}
__device__ __forceinline__ float sum2(unsigned long long v) {
    float lo, hi;
    asm("mov.b64 {%0, %1}, %2;" : "=f"(lo), "=f"(hi) : "l"(v));
    return lo + hi;
}

// ---- gate GEMM macros (group-parametrized) ----
#define GATES_L1(A1g, G1g, blo, bhi)                                           \
    {                                                                          \
        unsigned long long acc0[GROWS], acc1[GROWS];                           \
        _Pragma("unroll")                                                      \
        for (int r = 0; r < GROWS; ++r) {                                      \
            acc0[r] = pack2(blo, 0.0f);                                        \
            acc1[r] = pack2(bhi, 0.0f);                                        \
        }                                                                      \
        const int q0 = hf * 8;                                                 \
        _Pragma("unroll")                                                      \
        for (int q = 0; q < 8; ++q) {                                          \
            _Pragma("unroll")                                                  \
            for (int r = 0; r < GROWS; ++r) {                                  \
                ulonglong2 a = reinterpret_cast<const ulonglong2*>(&A1g[r][0])[q0 + q]; \
                acc0[r] = fma2(wL1[0][2 * q],     a.x, acc0[r]);               \
                acc0[r] = fma2(wL1[0][2 * q + 1], a.y, acc0[r]);               \
                acc1[r] = fma2(wL1[1][2 * q],     a.x, acc1[r]);               \
                acc1[r] = fma2(wL1[1][2 * q + 1], a.y, acc1[r]);               \
            }                                                                  \
        }                                                                      \
        _Pragma("unroll")                                                      \
        for (int r = 0; r < GROWS; ++r)                                        \
            *reinterpret_cast<float2*>(&G1g[hf][r][c0]) =                      \
                make_float2(sum2(acc0[r]), sum2(acc1[r]));                     \
    }

#define GATES_L2(A2g, G2g, blo, bhi)                                           \
    {                                                                          \
        unsigned long long acc0[GROWS], acc1[GROWS];                           \
        _Pragma("unroll")                                                      \
        for (int r = 0; r < GROWS; ++r) {                                      \
            acc0[r] = pack2(blo, 0.0f);                                        \
            acc1[r] = pack2(bhi, 0.0f);                                        \
        }                                                                      \
        const int q0 = hf * 13;                                                \
        _Pragma("unroll")                                                      \
        for (int q = 0; q < 13; ++q) {                                         \
            _Pragma("unroll")                                                  \
            for (int r = 0; r < GROWS; ++r) {                                  \
                ulonglong2 a = reinterpret_cast<const ulonglong2*>(&A2g[r][0])[q0 + q]; \
                acc0[r] = fma2(wL2[0][2 * q],     a.x, acc0[r]);               \
                acc0[r] = fma2(wL2[0][2 * q + 1], a.y, acc0[r]);               \
                acc1[r] = fma2(wL2[1][2 * q],     a.x, acc1[r]);               \
                acc1[r] = fma2(wL2[1][2 * q + 1], a.y, acc1[r]);               \
            }                                                                  \
        }                                                                      \
        _Pragma("unroll")                                                      \
        for (int r = 0; r < GROWS; ++r)                                        \
            *reinterpret_cast<float2*>(&G2g[hf][r][c0]) =                      \
                make_float2(sum2(acc0[r]), sum2(acc1[r]));                     \
    }

#define EPI_L1(G1g, A1g, A2g, c1g)                                             \
    {                                                                          \
        float gi = G1g[0][erow][en]          + G1g[1][erow][en];               \
        float gf = G1g[0][erow][NH + en]     + G1g[1][erow][NH + en];          \
        float gg = G1g[0][erow][2 * NH + en] + G1g[1][erow][2 * NH + en];      \
        float go = G1g[0][erow][3 * NH + en] + G1g[1][erow][3 * NH + en];      \
        c1g = siga(gf) * c1g + siga(gi) * tanha(gg);                           \
        float h = siga(go) * tanha(c1g);                                       \
        A1g[erow][D_IN + en] = h;                                              \
        A2g[erow][en]        = h;                                              \
    }

#define EPI_L2(G2g, A2g, POg, c2g)                                             \
    {                                                                          \
        float gi = G2g[0][erow][en]          + G2g[1][erow][en];               \
        float gf = G2g[0][erow][NH + en]     + G2g[1][erow][NH + en];          \
        float gg = G2g[0][erow][2 * NH + en] + G2g[1][erow][2 * NH + en];      \
        float go = G2g[0][erow][3 * NH + en] + G2g[1][erow][3 * NH + en];      \
        c2g = siga(gf) * c2g + siga(gi) * tanha(gg);                           \
        float h = siga(go) * tanha(c2g);                                       \
        A2g[erow][NH + en] = h;                                                \
        POg[erow][en] = h * wl;                                                \
    }

#define REDUCE_PO(POg, rowbase, step)                                          \
    {                                                                          \
        int r = tid >> 5, lane = tid & 31;                                     \
        float v = POg[r][lane] + POg[r][32 + lane];                            \
        _Pragma("unroll")                                                      \
        for (int off = 16; off > 0; off >>= 1)                                 \
            v += __shfl_down_sync(0xffffffffu, v, off);                        \
        if (lane == 0)                                                         \
            out[(mbase + (rowbase) + r) * T_STEPS + (step)] = v + bl;          \
    }

__global__ void __launch_bounds__(THREADS, 1)
lstm2_persistent_kernel(const float* __restrict__ x,
                        const float* __restrict__ Wih1, const float* __restrict__ Whh1,
                        const float* __restrict__ bih1, const float* __restrict__ bhh1,
                        const float* __restrict__ Wih2, const float* __restrict__ Whh2,
                        const float* __restrict__ bih2, const float* __restrict__ bhh2,
                        const float* __restrict__ Wlin, const float* __restrict__ blin,
                        float* __restrict__ out)
{
    __shared__ float A1A[GROWS][A1S], A1B[GROWS][A1S];
    __shared__ float A2A[GROWS][A2S], A2B[GROWS][A2S];
    __shared__ float G1A[2][GROWS][G4], G2A[2][GROWS][G4];   // [half][row][col]
    __shared__ float G1B[2][GROWS][G4], G2B[2][GROWS][G4];
    __shared__ float POA[GROWS][64], POB[GROWS][64];

    const int tid   = threadIdx.x;
    const int mbase = blockIdx.x * (2 * GROWS);
    const int hf    = tid >> 7;          // K-half, warp-uniform
    const int cp    = tid & 127;         // column-pair index
    const bool gate_active = (cp < CP);
    const int c0 = 2 * cp;               // first owned gate column

    // ---- ALL weights in per-thread registers (packed f32x2 k-pairs) ----
    unsigned long long wL1[2][16];       // 2 cols x half of padded K=64
    unsigned long long wL2[2][26];       // 2 cols x half of padded K=104
    #pragma unroll
    for (int c = 0; c < 2; ++c) {
        #pragma unroll
        for (int i = 0; i < 16; ++i) wL1[c][i] = 0ull;
        #pragma unroll
        for (int i = 0; i < 26; ++i) wL2[c][i] = 0ull;
    }
    if (gate_active) {
        #pragma unroll
        for (int c = 0; c < 2; ++c) {
            const int col = c0 + c;
            #pragma unroll
            for (int i = 0; i < 16; ++i) {
                int k0 = hf * 32 + 2 * i;
                float lo = 0.0f, hi = 0.0f;
                if (k0 < D_IN)            lo = Wih1[col * D_IN + k0];
                else if (k0 < D_IN + NH)  lo = Whh1[col * NH + (k0 - D_IN)];
                int k1 = k0 + 1;
                if (k1 < D_IN)            hi = Wih1[col * D_IN + k1];
                else if (k1 < D_IN + NH)  hi = Whh1[col * NH + (k1 - D_IN)];
                wL1[c][i] = pack2(lo, hi);
            }
            #pragma unroll
            for (int i = 0; i < 26; ++i) {
                int k0 = hf * 52 + 2 * i;
                float lo = 0.0f, hi = 0.0f;
                if (k0 < NH)            lo = Wih2[col * NH + k0];
                else if (k0 < 2 * NH)   lo = Whh2[col * NH + (k0 - NH)];
                int k1 = k0 + 1;
                if (k1 < NH)            hi = Wih2[col * NH + k1];
                else if (k1 < 2 * NH)   hi = Whh2[col * NH + (k1 - NH)];
                wL2[c][i] = pack2(lo, hi);
            }
        }
    }

    // gate biases (added only by K-half-0 threads)
    float b1lo = 0.0f, b1hi = 0.0f, b2lo = 0.0f, b2hi = 0.0f;
    if (gate_active && hf == 0) {
        b1lo = bih1[c0] + bhh1[c0];
        b1hi = bih1[c0 + 1] + bhh1[c0 + 1];
        b2lo = bih2[c0] + bhh2[c0];
        b2hi = bih2[c0 + 1] + bhh2[c0 + 1];
    }

    // ---- zero buffers, load x_0 for both groups ----
    for (int i = tid; i < GROWS * A1S; i += THREADS) {
        (&A1A[0][0])[i] = 0.0f; (&A1B[0][0])[i] = 0.0f;
    }
    for (int i = tid; i < GROWS * A2S; i += THREADS) {
        (&A2A[0][0])[i] = 0.0f; (&A2B[0][0])[i] = 0.0f;
    }
    for (int i = tid; i < GROWS * 64; i += THREADS) {
        (&POA[0][0])[i] = 0.0f; (&POB[0][0])[i] = 0.0f;
    }
    int pr = 0, pk = 0;
    if (tid < GROWS * D_IN) {
        pr = tid / D_IN; pk = tid - pr * D_IN;
        A1A[pr][pk] = x[(mbase + pr) * D_IN + pk];
        A1B[pr][pk] = x[(mbase + GROWS + pr) * D_IN + pk];
    }

    // epilogue mapping (tid < 102 -> (row-in-group, n)); cell states per group
    float wl = 0.0f, c1A = 0.0f, c2A = 0.0f, c1B = 0.0f, c2B = 0.0f;
    int erow = 0, en = 0;
    if (tid < CP) {
        erow = tid / NH;
        en   = tid - erow * NH;
        wl   = Wlin[en];
    }
    const float bl = blin[0];

    __syncthreads();

    float xrB = 0.0f;   // holds xB(i) for store at phase P(i)

    // Two groups, half-step offset:
    //  P(i): reduce POA(i-2) | gates A: L1(i), L2(i-1) | epilogue B step i-1 | store xB(i)
    //  Q(i): reduce POB(i-2) | gates B: L1(i), L2(i-1) | epilogue A step i   | store xA(i+1)
    for (int i = 0; i <= T_STEPS + 1; ++i) {
        // ===== Phase P =====
        float xrA = 0.0f;
        if (tid < GROWS * D_IN && (i + 1) < T_STEPS)
            xrA = x[((i + 1) * M_BATCH + mbase + pr) * D_IN + pk];

        if (i >= 2 && tid < 64) REDUCE_PO(POA, 0, i - 2);

        if (gate_active) {
            if (i < T_STEPS)            GATES_L1(A1A, G1A, b1lo, b1hi);
            if (i >= 1 && i <= T_STEPS) GATES_L2(A2A, G2A, b2lo, b2hi);
        }
        {   // epilogue for group B, step s = i-1
            const int s = i - 1;
            if (tid < CP) {
                if (s >= 0 && s < T_STEPS)  EPI_L1(G1B, A1B, A2B, c1B);
                if (s >= 1 && s <= T_STEPS) EPI_L2(G2B, A2B, POB, c2B);
            }
        }
        if (tid < GROWS * D_IN && i >= 1 && i < T_STEPS) A1B[pr][pk] = xrB;
        __syncthreads();

        // ===== Phase Q =====
        float xrBn = 0.0f;
        if (tid < GROWS * D_IN && (i + 1) < T_STEPS)
            xrBn = x[((i + 1) * M_BATCH + mbase + GROWS + pr) * D_IN + pk];

        if (i >= 2 && tid < 64) REDUCE_PO(POB, GROWS, i - 2);

        if (gate_active) {
            if (i < T_STEPS)            GATES_L1(A1B, G1B, b1lo, b1hi);
            if (i >= 1 && i <= T_STEPS) GATES_L2(A2B, G2B, b2lo, b2hi);
        }
        if (tid < CP) {  // epilogue for group A, step i
            if (i < T_STEPS)            EPI_L1(G1A, A1A, A2A, c1A);
            if (i >= 1 && i <= T_STEPS) EPI_L2(G2A, A2A, POA, c2A);
        }
        if (tid < GROWS * D_IN && (i + 1) < T_STEPS) A1A[pr][pk] = xrA;
        xrB = xrBn;
        __syncthreads();
    }
}

extern "C" void kernel_launch(void* const* d_in, const int* in_sizes, int n_in,
                              void* d_out, int out_size) {
    const float* x    = (const float*)d_in[0];
    const float* Wih1 = (const float*)d_in[1];
    const float* Whh1 = (const float*)d_in[2];
    const float* bih1 = (const float*)d_in[3];
    const float* bhh1 = (const float*)d_in[4];
    const float* Wih2 = (const float*)d_in[5];
    const float* Whh2 = (const float*)d_in[6];
    const float* bih2 = (const float*)d_in[7];
    const float* bhh2 = (const float*)d_in[8];
    const float* Wlin = (const float*)d_in[9];
    const float* blin = (const float*)d_in[10];
    float* out = (float*)d_out;

    lstm2_persistent_kernel<<<BLOCKS, THREADS>>>(
        x, Wih1, Whh1, bih1, bhh1, Wih2, Whh2, bih2, bhh2, Wlin, blin, out);
}